// round 16
// baseline (speedup 1.0000x reference)
#include <cuda_runtime.h>
#include <cuda_bf16.h>
#include <cuda_fp16.h>
#include <math.h>
#include <stdint.h>

#define S_  2048
#define H_  1024
#define NH_ 16
#define NKV_ 4
#define HD_ 64
#define QKV_O 1536
#define I_  2816
#define E_  8
#define WIN_ 512
#define EPS_ 1e-5f

typedef __nv_bfloat16 bf16;
typedef __half f16;
typedef unsigned long long u64;

// ---------------------------------------------------------------------------
// Scratch (static device globals)
// ---------------------------------------------------------------------------
__device__ bf16 g_wqkv_h[QKV_O * H_], g_wqkv_l[QKV_O * H_];
__device__ bf16 g_wo_h[H_ * H_],      g_wo_l[H_ * H_];
__device__ f16  g_ws_f[(size_t)E_ * 2 * I_ * H_];
__device__ f16  g_w2s_f[(size_t)E_ * H_ * I_];
__device__ bf16 g_xn_h[S_ * H_], g_xn_l[S_ * H_];
__device__ bf16 g_at_h[S_ * H_], g_at_l[S_ * H_];
__device__ f16  g_tn_f[S_ * H_];
__device__ float g_tnorm[S_ * H_];
__device__ f16  g_act_f[(size_t)E_ * S_ * I_];
__device__ f16  g_y[(size_t)E_ * S_ * H_];         // per-slot MoE outputs (fp16)
__device__ float g_qkv[S_ * QKV_O];
__device__ int   g_counts[E_];
__device__ int   g_toklist[E_ * S_];
__device__ int   g_tokslot[S_ * 2];
__device__ float g_tokw2[S_ * 2];

// ---------------------------------------------------------------------------
__device__ __forceinline__ uint32_t smem_u32(const void* p) {
    uint32_t a;
    asm("{ .reg .u64 t; cvta.to.shared.u64 t, %1; cvt.u32.u64 %0, t; }"
        : "=r"(a) : "l"(p));
    return a;
}
__device__ __forceinline__ void ldm4(uint32_t& r0, uint32_t& r1,
                                     uint32_t& r2, uint32_t& r3, uint32_t addr) {
    asm volatile("ldmatrix.sync.aligned.m8n8.x4.shared.b16 {%0,%1,%2,%3}, [%4];"
                 : "=r"(r0), "=r"(r1), "=r"(r2), "=r"(r3) : "r"(addr));
}
__device__ __forceinline__ void mma_bf16(float* d, const uint32_t* a,
                                         const uint32_t* b) {
    asm volatile(
        "mma.sync.aligned.m16n8k16.row.col.f32.bf16.bf16.f32 "
        "{%0,%1,%2,%3}, {%4,%5,%6,%7}, {%8,%9}, {%0,%1,%2,%3};"
        : "+f"(d[0]), "+f"(d[1]), "+f"(d[2]), "+f"(d[3])
        : "r"(a[0]), "r"(a[1]), "r"(a[2]), "r"(a[3]), "r"(b[0]), "r"(b[1]));
}
__device__ __forceinline__ void mma_f16(float* d, const uint32_t* a,
                                        const uint32_t* b) {
    asm volatile(
        "mma.sync.aligned.m16n8k16.row.col.f32.f16.f16.f32 "
        "{%0,%1,%2,%3}, {%4,%5,%6,%7}, {%8,%9}, {%0,%1,%2,%3};"
        : "+f"(d[0]), "+f"(d[1]), "+f"(d[2]), "+f"(d[3])
        : "r"(a[0]), "r"(a[1]), "r"(a[2]), "r"(a[3]), "r"(b[0]), "r"(b[1]));
}
__device__ __forceinline__ void cp16(uint32_t dst, const void* src, int sz) {
    asm volatile("cp.async.cg.shared.global [%0], [%1], 16, %2;"
                 :: "r"(dst), "l"(src), "r"(sz));
}
__device__ __forceinline__ void cp_commit() {
    asm volatile("cp.async.commit_group;");
}
__device__ __forceinline__ void cp_wait0() {
    asm volatile("cp.async.wait_group 0;");
}
__device__ __forceinline__ void cp_wait1() {
    asm volatile("cp.async.wait_group 1;");
}

// packed f32x2 helpers
__device__ __forceinline__ u64 pack2(float lo, float hi) {
    u64 r; asm("mov.b64 %0, {%1,%2};" : "=l"(r) : "f"(lo), "f"(hi)); return r;
}
__device__ __forceinline__ void unpack2(u64 v, float& lo, float& hi) {
    asm("mov.b64 {%0,%1}, %2;" : "=f"(lo), "=f"(hi) : "l"(v));
}
__device__ __forceinline__ void ffma2(u64& d, u64 a, u64 b) {
    asm("fma.rn.f32x2 %0, %1, %2, %0;" : "+l"(d) : "l"(a), "l"(b));
}
__device__ __forceinline__ void mulf2(u64& d, u64 a) {
    asm("mul.rn.f32x2 %0, %0, %1;" : "+l"(d) : "l"(a));
}

// split fp32 float4 -> bf16 hi/lo (8B each)
__device__ __forceinline__ void split_store4(float4 v, bf16* hp, bf16* lp) {
    __nv_bfloat162 h01 = __floats2bfloat162_rn(v.x, v.y);
    __nv_bfloat162 h23 = __floats2bfloat162_rn(v.z, v.w);
    float2 f01 = __bfloat1622float2(h01);
    float2 f23 = __bfloat1622float2(h23);
    __nv_bfloat162 l01 = __floats2bfloat162_rn(v.x - f01.x, v.y - f01.y);
    __nv_bfloat162 l23 = __floats2bfloat162_rn(v.z - f23.x, v.w - f23.y);
    *(uint2*)hp = make_uint2(*(uint32_t*)&h01, *(uint32_t*)&h23);
    *(uint2*)lp = make_uint2(*(uint32_t*)&l01, *(uint32_t*)&l23);
}
__device__ __forceinline__ void split1(float v, bf16* hp, bf16* lp) {
    bf16 hb = __float2bfloat16(v);
    *hp = hb;
    *lp = __float2bfloat16(v - __bfloat162float(hb));
}
__device__ __forceinline__ void cvt_store4(float4 v, f16* p) {
    __half2 a = __floats2half2_rn(v.x, v.y);
    __half2 b = __floats2half2_rn(v.z, v.w);
    *(uint2*)p = make_uint2(*(uint32_t*)&a, *(uint32_t*)&b);
}

// ---------------------------------------------------------------------------
// hmma2: bf16 3-term split GEMM (router-critical path).
// CTA tile 128 x (NF*32), BK=32, 8 warps (2m x 4n), warp tile 64 x (NF*8).
// cp.async double-buffered, MAXCTA CTAs/SM.  EPI: 0=store 1=+addsrc
// NF=4: 128-wide tile (O-proj).  NF=6: 192-wide tile (QKV, 1 CTA/SM,
// single balanced wave: grid 16x8=128 CTAs).
// ---------------------------------------------------------------------------
template<int NF, int MAXCTA, int EPI>
__global__ __launch_bounds__(256, MAXCTA)
void hmma2(const bf16* __restrict__ Ah, const bf16* __restrict__ Al,
           const bf16* __restrict__ Bh, const bf16* __restrict__ Bl,
           float* __restrict__ C, int M, int N, int K, int lda, int ldc,
           const float* __restrict__ addsrc)
{
    extern __shared__ char smem[];
    const int TILE_N = NF * 32;
    const int BPS = TILE_N * 64;            // B plane bytes per stage
    const int STAGE = 16384 + 2 * BPS;      // A planes 16KB + 2 B planes

    int m0 = blockIdx.x * 128;
    int n0 = blockIdx.y * TILE_N;

    int tid = threadIdx.x;
    int wid = tid >> 5;
    int lane = tid & 31;
    int warp_m = wid & 1;
    int warp_n = wid >> 1;

    uint32_t sbase = smem_u32(smem);

    auto issue = [&](int c, int buf) {
        int k0 = c * 32;
        #pragma unroll
        for (int l = 0; l < 4 + NF; l++) {
            int seg = tid + l * 256;
            uint32_t dst;
            const bf16* gsrc;
            if (seg < 1024) {               // A planes
                int plane = seg >> 9;
                int rem = seg & 511;
                int row = rem >> 2, ch = rem & 3;
                dst = sbase + buf * STAGE + plane * 8192
                    + row * 64 + ((ch ^ ((row >> 1) & 3)) << 4);
                gsrc = (plane ? Al : Ah) + (size_t)(m0 + row) * lda + k0 + ch * 8;
            } else {                        // B planes
                int s2 = seg - 1024;
                int plane = s2 / (NF * 128);
                int rem = s2 - plane * (NF * 128);
                int row = rem >> 2, ch = rem & 3;
                dst = sbase + buf * STAGE + 16384 + plane * BPS
                    + row * 64 + ((ch ^ ((row >> 1) & 3)) << 4);
                gsrc = (plane ? Bl : Bh) + (size_t)(n0 + row) * K + k0 + ch * 8;
            }
            cp16(dst, gsrc, 16);
        }
        cp_commit();
    };

    float acc[4][NF][4];
    #pragma unroll
    for (int mf = 0; mf < 4; mf++)
        #pragma unroll
        for (int nf = 0; nf < NF; nf++)
            #pragma unroll
            for (int q = 0; q < 4; q++) acc[mf][nf][q] = 0.f;

    const int nc = K / 32;
    issue(0, 0);

    for (int c = 0; c < nc; c++) {
        cp_wait0();
        __syncthreads();
        if (c + 1 < nc) issue(c + 1, (c + 1) & 1);

        uint32_t sb = sbase + (c & 1) * STAGE;
        int mi = lane >> 3, r = lane & 7;

        #pragma unroll
        for (int ks = 0; ks < 2; ks++) {
            uint32_t afh[4][4], bfh[NF][2];
            #pragma unroll
            for (int nfp = 0; nfp < NF / 2; nfp++) {
                int n = warp_n * (NF * 8) + nfp * 16 + ((mi >> 1) << 3) + r;
                int ch = ks * 2 + (mi & 1);
                uint32_t off = (uint32_t)(n * 64 + ((ch ^ ((n >> 1) & 3)) << 4));
                uint32_t r0, r1, r2, r3;
                ldm4(r0, r1, r2, r3, sb + 16384 + off);
                bfh[nfp * 2 + 0][0] = r0; bfh[nfp * 2 + 0][1] = r1;
                bfh[nfp * 2 + 1][0] = r2; bfh[nfp * 2 + 1][1] = r3;
            }
            #pragma unroll
            for (int mf = 0; mf < 4; mf++) {
                int row = warp_m * 64 + mf * 16 + ((mi & 1) << 3) + r;
                int ch = ks * 2 + (mi >> 1);
                uint32_t off = (uint32_t)(row * 64 + ((ch ^ ((row >> 1) & 3)) << 4));
                ldm4(afh[mf][0], afh[mf][1], afh[mf][2], afh[mf][3], sb + off);
            }
            #pragma unroll
            for (int mf = 0; mf < 4; mf++)
                #pragma unroll
                for (int nf = 0; nf < NF; nf++)
                    mma_bf16(acc[mf][nf], afh[mf], bfh[nf]);
            {
                uint32_t bfl[NF][2];
                #pragma unroll
                for (int nfp = 0; nfp < NF / 2; nfp++) {
                    int n = warp_n * (NF * 8) + nfp * 16 + ((mi >> 1) << 3) + r;
                    int ch = ks * 2 + (mi & 1);
                    uint32_t off = (uint32_t)(n * 64 + ((ch ^ ((n >> 1) & 3)) << 4));
                    uint32_t r0, r1, r2, r3;
                    ldm4(r0, r1, r2, r3, sb + 16384 + BPS + off);
                    bfl[nfp * 2 + 0][0] = r0; bfl[nfp * 2 + 0][1] = r1;
                    bfl[nfp * 2 + 1][0] = r2; bfl[nfp * 2 + 1][1] = r3;
                }
                #pragma unroll
                for (int mf = 0; mf < 4; mf++)
                    #pragma unroll
                    for (int nf = 0; nf < NF; nf++)
                        mma_bf16(acc[mf][nf], afh[mf], bfl[nf]);
            }
            {
                uint32_t afl[4][4];
                #pragma unroll
                for (int mf = 0; mf < 4; mf++) {
                    int row = warp_m * 64 + mf * 16 + ((mi & 1) << 3) + r;
                    int ch = ks * 2 + (mi >> 1);
                    uint32_t off = (uint32_t)(row * 64 + ((ch ^ ((row >> 1) & 3)) << 4));
                    ldm4(afl[mf][0], afl[mf][1], afl[mf][2], afl[mf][3], sb + 8192 + off);
                }
                #pragma unroll
                for (int mf = 0; mf < 4; mf++)
                    #pragma unroll
                    for (int nf = 0; nf < NF; nf++)
                        mma_bf16(acc[mf][nf], afl[mf], bfh[nf]);
            }
        }
    }

    int lr = lane >> 2;
    int lc = (lane & 3) * 2;
    #pragma unroll
    for (int mf = 0; mf < 4; mf++) {
        int r0g = m0 + warp_m * 64 + mf * 16 + lr;
        int r1g = r0g + 8;
        #pragma unroll
        for (int nf = 0; nf < NF; nf++) {
            int col = n0 + warp_n * (NF * 8) + nf * 8 + lc;
            float2 v = make_float2(acc[mf][nf][0], acc[mf][nf][1]);
            float2 w = make_float2(acc[mf][nf][2], acc[mf][nf][3]);
            if (EPI == 1) {
                const float* a2 = addsrc + (size_t)r0g * ldc + col;
                const float* b2 = addsrc + (size_t)r1g * ldc + col;
                v.x += a2[0]; v.y += a2[1];
                w.x += b2[0]; w.y += b2[1];
            }
            *(float2*)(C + (size_t)r0g * ldc + col) = v;
            *(float2*)(C + (size_t)r1g * ldc + col) = w;
        }
    }
}

// ---------------------------------------------------------------------------
// hmma1: plain fp16 GEMM (MoE path). 128x128 tile, BK=64, 8 warps,
// 3-stage cp.async pipeline, 2 CTAs/SM.
// GATHER: A rows via toklist.
// EPI: 0=dense per-slot fp16 store to C (ldc)  3=swiglu->act fp16
// ---------------------------------------------------------------------------
template<int GATHER, int EPI>
__global__ __launch_bounds__(256, 2)
void hmma1(const f16* __restrict__ A, const f16* __restrict__ B,
           f16* __restrict__ C, int M, int N, int K, int lda, int ldc,
           const int* __restrict__ counts,
           const int* __restrict__ toklist,
           f16* __restrict__ actF,
           size_t sA, size_t sB, size_t sC)
{
    extern __shared__ char smem[];
    __shared__ int rowsS[128];

    int e = blockIdx.z;
    int Mlim = counts[e];
    int m0 = blockIdx.x * 128;
    if (m0 >= Mlim) return;
    int n0 = blockIdx.y * 128;
    const f16* Ae = A + sA * e;
    const f16* Be = B + sB * e;
    f16*       Ce = C ? C + sC * e : nullptr;

    int tid = threadIdx.x;
    int wid = tid >> 5;
    int lane = tid & 31;
    int warp_m = wid & 1;
    int warp_n = wid >> 1;

    if (GATHER) {
        if (tid < 128)
            rowsS[tid] = (m0 + tid < Mlim) ? toklist[e * S_ + m0 + tid] : -1;
        __syncthreads();
    }

    uint32_t sbase = smem_u32(smem);

    auto issue = [&](int c, int buf) {
        int k0 = c * 64;
        #pragma unroll
        for (int l = 0; l < 8; l++) {
            int seg = tid + l * 256;
            int plane = seg >> 10;
            int row = (seg >> 3) & 127;
            int ch = seg & 7;
            uint32_t dst = sbase + buf * 32768 + plane * 16384
                         + row * 128 + ((ch ^ (row & 7)) << 4);
            const f16* gsrc;
            int sz = 16;
            if (plane == 0) {
                int gr;
                if (GATHER) {
                    gr = rowsS[row];
                    if (gr < 0) { gr = 0; sz = 0; }
                } else {
                    gr = m0 + row;
                    if (gr >= Mlim) { gr = 0; sz = 0; }
                }
                gsrc = Ae + (size_t)gr * lda + k0 + ch * 8;
            } else {
                gsrc = Be + (size_t)(n0 + row) * K + k0 + ch * 8;
            }
            cp16(dst, gsrc, sz);
        }
        cp_commit();
    };

    float acc[4][4][4] = {};
    const int nc = K / 64;
    issue(0, 0);
    if (nc > 1) issue(1, 1);

    for (int c = 0; c < nc; c++) {
        if (c + 1 < nc) cp_wait1(); else cp_wait0();
        __syncthreads();
        if (c + 2 < nc) issue(c + 2, (c + 2) % 3);

        uint32_t sb = sbase + (c % 3) * 32768;
        int mi = lane >> 3, r = lane & 7;

        #pragma unroll
        for (int ks = 0; ks < 4; ks++) {
            uint32_t af[4][4], bf[4][2];
            #pragma unroll
            for (int nfp = 0; nfp < 2; nfp++) {
                int n = warp_n * 32 + nfp * 16 + ((mi >> 1) << 3) + r;
                int ch = ks * 2 + (mi & 1);
                uint32_t off = (uint32_t)(n * 128 + ((ch ^ (n & 7)) << 4));
                uint32_t r0, r1, r2, r3;
                ldm4(r0, r1, r2, r3, sb + 16384 + off);
                bf[nfp * 2 + 0][0] = r0; bf[nfp * 2 + 0][1] = r1;
                bf[nfp * 2 + 1][0] = r2; bf[nfp * 2 + 1][1] = r3;
            }
            #pragma unroll
            for (int mf = 0; mf < 4; mf++) {
                int row = warp_m * 64 + mf * 16 + ((mi & 1) << 3) + r;
                int ch = ks * 2 + (mi >> 1);
                uint32_t off = (uint32_t)(row * 128 + ((ch ^ (row & 7)) << 4));
                ldm4(af[mf][0], af[mf][1], af[mf][2], af[mf][3], sb + off);
            }
            #pragma unroll
            for (int mf = 0; mf < 4; mf++)
                #pragma unroll
                for (int nf = 0; nf < 4; nf++)
                    mma_f16(acc[mf][nf], af[mf], bf[nf]);
        }
    }

    int lr = lane >> 2;
    int lc = (lane & 3) * 2;

    if (EPI == 3) {
        __syncthreads();
        float (*Us)[65] = (float (*)[65])smem;
        if (warp_n >= 2) {
            #pragma unroll
            for (int mf = 0; mf < 4; mf++) {
                int rl0 = warp_m * 64 + mf * 16 + lr;
                #pragma unroll
                for (int nf = 0; nf < 4; nf++) {
                    int j = (warp_n - 2) * 32 + nf * 8 + lc;
                    Us[rl0][j]         = acc[mf][nf][0];
                    Us[rl0][j + 1]     = acc[mf][nf][1];
                    Us[rl0 + 8][j]     = acc[mf][nf][2];
                    Us[rl0 + 8][j + 1] = acc[mf][nf][3];
                }
            }
        }
        __syncthreads();
        if (warp_n < 2) {
            int colbase = n0 >> 1;
            #pragma unroll
            for (int mf = 0; mf < 4; mf++) {
                int rl0 = warp_m * 64 + mf * 16 + lr;
                #pragma unroll
                for (int half = 0; half < 2; half++) {
                    int rl = rl0 + half * 8;
                    int m = m0 + rl;
                    if (m >= Mlim) continue;
                    size_t rowoff = ((size_t)e * S_ + m) * I_ + colbase;
                    #pragma unroll
                    for (int nf = 0; nf < 4; nf++) {
                        int j = warp_n * 32 + nf * 8 + lc;
                        #pragma unroll
                        for (int q = 0; q < 2; q++) {
                            float g = acc[mf][nf][half * 2 + q];
                            float u = Us[rl][j + q];
                            float a = g / (1.f + __expf(-g)) * u;
                            actF[rowoff + j + q] = __float2half_rn(a);
                        }
                    }
                }
            }
        }
        return;
    }

    // EPI == 0: dense per-slot fp16 store
    #pragma unroll
    for (int mf = 0; mf < 4; mf++) {
        int r0g = m0 + warp_m * 64 + mf * 16 + lr;
        int r1g = r0g + 8;
        #pragma unroll
        for (int nf = 0; nf < 4; nf++) {
            int col = n0 + warp_n * 32 + nf * 8 + lc;
            if (r0g < Mlim) {
                __half2 h = __floats2half2_rn(acc[mf][nf][0], acc[mf][nf][1]);
                *(uint32_t*)(Ce + (size_t)r0g * ldc + col) = *(uint32_t*)&h;
            }
            if (r1g < Mlim) {
                __half2 h = __floats2half2_rn(acc[mf][nf][2], acc[mf][nf][3]);
                *(uint32_t*)(Ce + (size_t)r1g * ldc + col) = *(uint32_t*)&h;
            }
        }
    }
}

// ---------------------------------------------------------------------------
__global__ void split_kernel(const float* __restrict__ src,
                             bf16* __restrict__ h, bf16* __restrict__ l,
                             size_t n4) {
    size_t i = (size_t)blockIdx.x * blockDim.x + threadIdx.x;
    if (i >= n4) return;
    float4 v = ((const float4*)src)[i];
    split_store4(v, h + i * 4, l + i * 4);
}

// Fused MoE weight conversion, grid-stride over a partial-width grid.
// 2x unrolled independent loads per iteration for MLP.
__global__ void cvt_moe_gs(const float* __restrict__ ws, f16* __restrict__ dws,
                           const float* __restrict__ w2s, f16* __restrict__ dw2) {
    int nblk = gridDim.x;
    // part 1: ws permuted rows (process 2 rows per iteration for MLP)
    for (int p = blockIdx.x * 2; p < E_ * 2 * I_; p += nblk * 2) {
        #pragma unroll
        for (int q = 0; q < 2; q++) {
            int pp = p + q;
            if (pp >= E_ * 2 * I_) break;
            int e = pp / (2 * I_);
            int pr = pp % (2 * I_);
            int t = pr >> 7, r = pr & 127;
            int src = (r < 64) ? (t * 64 + r) : (I_ + t * 64 + (r - 64));
            const float* srow = ws + ((size_t)e * 2 * I_ + src) * H_;
            f16* dr = dws + ((size_t)e * 2 * I_ + pr) * H_;
            int i = threadIdx.x * 4;
            float4 v = *(const float4*)(srow + i);
            cvt_store4(v, dr + i);
        }
    }
    // part 2: flat w2s conversion, 2 independent float4 per iteration
    size_t n4 = (size_t)E_ * H_ * I_ / 4;
    size_t stride = (size_t)nblk * 256;
    for (size_t i = (size_t)blockIdx.x * 256 + threadIdx.x; i < n4;
         i += stride * 2) {
        size_t i2 = i + stride;
        float4 v0 = ((const float4*)w2s)[i];
        if (i2 < n4) {
            float4 v1 = ((const float4*)w2s)[i2];
            cvt_store4(v0, dw2 + i * 4);
            cvt_store4(v1, dw2 + i2 * 4);
        } else {
            cvt_store4(v0, dw2 + i * 4);
        }
    }
}

// ---------------------------------------------------------------------------
__global__ void zero_counts(int* counts) {
    if (threadIdx.x < E_) counts[threadIdx.x] = 0;
}

// RMSNorm -> bf16 hi/lo planes (ln1 path)
__global__ void rmsnorm_hl(const float* __restrict__ x,
                           const float* __restrict__ w,
                           bf16* __restrict__ yh, bf16* __restrict__ yl) {
    int row = blockIdx.x;
    int tid = threadIdx.x;
    __shared__ float red[256];
    const float* xr = x + (size_t)row * H_;
    float s = 0.0f;
    for (int c = tid; c < H_; c += 256) { float v = xr[c]; s += v * v; }
    red[tid] = s; __syncthreads();
    for (int o = 128; o > 0; o >>= 1) {
        if (tid < o) red[tid] += red[tid + o];
        __syncthreads();
    }
    float inv = rsqrtf(red[0] / (float)H_ + EPS_);
    for (int c = tid * 4; c < H_; c += 1024) {
        float4 v = *(const float4*)(xr + c);
        float4 wv = *(const float4*)(w + c);
        v.x *= inv * wv.x; v.y *= inv * wv.y;
        v.z *= inv * wv.z; v.w *= inv * wv.w;
        split_store4(v, yh + (size_t)row * H_ + c, yl + (size_t)row * H_ + c);
    }
}

// RMSNorm -> fp32 (router input — MUST stay fp32) + fp16 plane (MoE A)
__global__ void rmsnorm_f16(const float* __restrict__ x,
                            const float* __restrict__ w,
                            float* __restrict__ y,
                            f16* __restrict__ yf) {
    int row = blockIdx.x;
    int tid = threadIdx.x;
    __shared__ float red[256];
    const float* xr = x + (size_t)row * H_;
    float s = 0.0f;
    for (int c = tid; c < H_; c += 256) { float v = xr[c]; s += v * v; }
    red[tid] = s; __syncthreads();
    for (int o = 128; o > 0; o >>= 1) {
        if (tid < o) red[tid] += red[tid + o];
        __syncthreads();
    }
    float inv = rsqrtf(red[0] / (float)H_ + EPS_);
    for (int c = tid * 4; c < H_; c += 1024) {
        float4 v = *(const float4*)(xr + c);
        float4 wv = *(const float4*)(w + c);
        v.x *= inv * wv.x; v.y *= inv * wv.y;
        v.z *= inv * wv.z; v.w *= inv * wv.w;
        *(float4*)(y + (size_t)row * H_ + c) = v;
        cvt_store4(v, yf + (size_t)row * H_ + c);
    }
}

// ---------------------------------------------------------------------------
// Flash attention (fp32, f32x2-packed math): 128 threads, 8x4 register tile
// ---------------------------------------------------------------------------
__global__ __launch_bounds__(128)
void attn_flash(const float* __restrict__ qkv,
                bf16* __restrict__ oh, bf16* __restrict__ ol) {
    extern __shared__ float smf[];
    float* Qs  = smf;
    float* KPs = smf + 4096;
    float* Vs  = smf + 4096 + 64 * 68;

    int qt = blockIdx.x, h = blockIdx.y;
    int q0 = qt * 64;
    int kvh = h >> 2;
    int tid = threadIdx.x;
    int tx = tid & 15, ty = tid >> 4;

    #pragma unroll
    for (int l = 0; l < 8; l++) {
        int idx = tid + l * 128;
        int r = idx >> 4, dq = (idx & 15) * 4;
        *(float4*)&Qs[r * 64 + dq] =
            *(const float4*)&qkv[(size_t)(q0 + r) * QKV_O + h * 64 + dq];
    }

    u64 acc2[8][4];
    #pragma unroll
    for (int i = 0; i < 8; i++)
        #pragma unroll
        for (int j = 0; j < 4; j++) acc2[i][j] = 0ull;
    float rm[8], rl[8];
    #pragma unroll
    for (int i = 0; i < 8; i++) { rm[i] = -1e30f; rl[i] = 0.f; }

    int t0 = (q0 > 511) ? ((q0 - 511) >> 6) : 0;
    for (int kt = t0; kt <= qt; kt++) {
        int j0 = kt * 64;
        __syncthreads();
        #pragma unroll
        for (int l = 0; l < 8; l++) {
            int idx = tid + l * 128;
            int r = idx >> 4, dq = (idx & 15) * 4;
            *(float4*)&KPs[r * 68 + dq] =
                *(const float4*)&qkv[(size_t)(j0 + r) * QKV_O + H_ + kvh * 64 + dq];
            *(float4*)&Vs[r * 64 + dq] =
                *(const float4*)&qkv[(size_t)(j0 + r) * QKV_O + H_ + NKV_ * HD_ + kvh * 64 + dq];
        }
        __syncthreads();

        u64 s2[8][4];
        #pragma unroll
        for (int i = 0; i < 8; i++)
            #pragma unroll
            for (int j = 0; j < 4; j++) s2[i][j] = 0ull;
        #pragma unroll
        for (int d0 = 0; d0 < 64; d0 += 4) {
            u64 ka[4], kb[4];
            #pragma unroll
            for (int j = 0; j < 4; j++) {
                const u64* kp = (const u64*)&KPs[(tx + 16 * j) * 68 + d0];
                ka[j] = kp[0]; kb[j] = kp[1];
            }
            #pragma unroll
            for (int i = 0; i < 8; i++) {
                const u64* qp = (const u64*)&Qs[(ty * 8 + i) * 64 + d0];
                u64 qa = qp[0], qb = qp[1];
                #pragma unroll
                for (int j = 0; j < 4; j++) {
                    ffma2(s2[i][j], qa, ka[j]);
                    ffma2(s2[i][j], qb, kb[j]);
                }
            }
        }
        __syncthreads();

        #pragma unroll
        for (int i = 0; i < 8; i++) {
            int iq = q0 + ty * 8 + i;
            float p[4], s[4];
            float tm = -1e30f;
            #pragma unroll
            for (int j = 0; j < 4; j++) {
                float lo, hi;
                unpack2(s2[i][j], lo, hi);
                int jk = j0 + tx + 16 * j;
                bool ok = (jk <= iq) && (iq - jk < WIN_);
                s[j] = ok ? (lo + hi) * 0.125f : -1e30f;
                tm = fmaxf(tm, s[j]);
            }
            #pragma unroll
            for (int o = 1; o < 16; o <<= 1)
                tm = fmaxf(tm, __shfl_xor_sync(0xffffffffu, tm, o));
            float mn = fmaxf(rm[i], tm);
            float alpha = __expf(rm[i] - mn);
            rm[i] = mn;
            float ps = 0.f;
            #pragma unroll
            for (int j = 0; j < 4; j++) { p[j] = __expf(s[j] - mn); ps += p[j]; }
            #pragma unroll
            for (int o = 1; o < 16; o <<= 1)
                ps += __shfl_xor_sync(0xffffffffu, ps, o);
            rl[i] = rl[i] * alpha + ps;
            u64 alpha2 = pack2(alpha, alpha);
            #pragma unroll
            for (int j = 0; j < 4; j++) {
                mulf2(acc2[i][j], alpha2);
                KPs[(ty * 8 + i) * 68 + tx + 16 * j] = p[j];
            }
        }
        __syncthreads();

        #pragma unroll 2
        for (int n = 0; n < 64; n += 2) {
            u64 pv2[8];
            #pragma unroll
            for (int i = 0; i < 8; i++)
                pv2[i] = *(const u64*)&KPs[(ty * 8 + i) * 68 + n];
            u64 v2[4];
            #pragma unroll
            for (int j = 0; j < 4; j++)
                v2[j] = pack2(Vs[n * 64 + tx + 16 * j],
                              Vs[(n + 1) * 64 + tx + 16 * j]);
            #pragma unroll
            for (int i = 0; i < 8; i++)
                #pragma unroll
                for (int j = 0; j < 4; j++)
                    ffma2(acc2[i][j], pv2[i], v2[j]);
        }
    }

    #pragma unroll
    for (int i = 0; i < 8; i++) {
        float inv = 1.0f / rl[i];
        size_t base = (size_t)(q0 + ty * 8 + i) * H_ + h * 64;
        #pragma unroll
        for (int j = 0; j < 4; j++) {
            float lo, hi;
            unpack2(acc2[i][j], lo, hi);
            split1((lo + hi) * inv, &oh[base + tx + 16 * j], &ol[base + tx + 16 * j]);
        }
    }
}

// ---------------------------------------------------------------------------
// Router reads fp32 tnorm (router-critical precision)
__global__ void router_kernel(const float* __restrict__ t,
                              const float* __restrict__ rw,
                              int* counts, int* toklist,
                              int* tokslot, float* tokw2) {
    int warp = threadIdx.x >> 5;
    int lane = threadIdx.x & 31;
    int tok = blockIdx.x * 8 + warp;
    if (tok >= S_) return;
    const float* tr = t + (size_t)tok * H_;
    float logits[E_];
    for (int e = 0; e < E_; e++) {
        float s = 0.0f;
        for (int k = lane; k < H_; k += 32) s += tr[k] * rw[e * H_ + k];
        for (int o = 16; o > 0; o >>= 1) s += __shfl_xor_sync(0xffffffff, s, o);
        logits[e] = s;
    }
    if (lane == 0) {
        float mx = logits[0];
        for (int e = 1; e < E_; e++) mx = fmaxf(mx, logits[e]);
        float p[E_], sum = 0.0f;
        for (int e = 0; e < E_; e++) { p[e] = __expf(logits[e] - mx); sum += p[e]; }
        float invs = 1.0f / sum;
        for (int e = 0; e < E_; e++) p[e] *= invs;
        int b1 = 0;
        for (int e = 1; e < E_; e++) if (p[e] > p[b1]) b1 = e;
        int b2 = -1;
        for (int e = 0; e < E_; e++) {
            if (e == b1) continue;
            if (b2 < 0 || p[e] > p[b2]) b2 = e;
        }
        int pos1 = atomicAdd(&counts[b1], 1);
        toklist[b1 * S_ + pos1] = tok;
        tokslot[tok * 2] = b1 * S_ + pos1; tokw2[tok * 2] = p[b1];
        int pos2 = atomicAdd(&counts[b2], 1);
        toklist[b2 * S_ + pos2] = tok;
        tokslot[tok * 2 + 1] = b2 * S_ + pos2; tokw2[tok * 2 + 1] = p[b2];
    }
}

// out[tok] = w1 * y[slot1] + w2 * y[slot2]   (y is fp16)
__global__ void combine_kernel(const f16* __restrict__ y,
                               const int* __restrict__ tokslot,
                               const float* __restrict__ tokw2,
                               float* __restrict__ out) {
    int tok = blockIdx.x;
    int c = threadIdx.x * 4;
    int s1 = tokslot[tok * 2], s2 = tokslot[tok * 2 + 1];
    float w1 = tokw2[tok * 2], w2 = tokw2[tok * 2 + 1];
    uint2 ar = *(const uint2*)&y[(size_t)s1 * H_ + c];
    uint2 br = *(const uint2*)&y[(size_t)s2 * H_ + c];
    float2 a0 = __half22float2(*(__half2*)&ar.x);
    float2 a1 = __half22float2(*(__half2*)&ar.y);
    float2 b0 = __half22float2(*(__half2*)&br.x);
    float2 b1 = __half22float2(*(__half2*)&br.y);
    float4 o;
    o.x = w1 * a0.x + w2 * b0.x;
    o.y = w1 * a0.y + w2 * b0.y;
    o.z = w1 * a1.x + w2 * b1.x;
    o.w = w1 * a1.y + w2 * b1.y;
    *(float4*)&out[(size_t)tok * H_ + c] = o;
}

// ---------------------------------------------------------------------------
extern "C" void kernel_launch(void* const* d_in, const int* in_sizes, int n_in,
                              void* d_out, int out_size) {
    const float* hidden   = (const float*)d_in[0];
    const float* w_qkv    = (const float*)d_in[2];
    const float* w_o      = (const float*)d_in[3];
    const float* router_w = (const float*)d_in[4];
    const float* ws       = (const float*)d_in[5];
    const float* w2s      = (const float*)d_in[6];
    const float* ln1      = (const float*)d_in[7];
    const float* ln2      = (const float*)d_in[8];

    float* out    = (float*)d_out;
    float* resid2 = out + (size_t)S_ * H_;

    bf16 *wqh, *wql, *woh, *wol, *xnh, *xnl, *ath, *atl;
    f16 *wsf, *w2f, *tnf, *actf, *yb;
    float *qkv, *tnorm, *tokw2;
    int *counts, *toklist, *tokslot;
    cudaGetSymbolAddress((void**)&wqh, g_wqkv_h); cudaGetSymbolAddress((void**)&wql, g_wqkv_l);
    cudaGetSymbolAddress((void**)&woh, g_wo_h);   cudaGetSymbolAddress((void**)&wol, g_wo_l);
    cudaGetSymbolAddress((void**)&wsf, g_ws_f);
    cudaGetSymbolAddress((void**)&w2f, g_w2s_f);
    cudaGetSymbolAddress((void**)&xnh, g_xn_h);   cudaGetSymbolAddress((void**)&xnl, g_xn_l);
    cudaGetSymbolAddress((void**)&ath, g_at_h);   cudaGetSymbolAddress((void**)&atl, g_at_l);
    cudaGetSymbolAddress((void**)&tnf, g_tn_f);
    cudaGetSymbolAddress((void**)&tnorm, g_tnorm);
    cudaGetSymbolAddress((void**)&actf, g_act_f);
    cudaGetSymbolAddress((void**)&yb, g_y);
    cudaGetSymbolAddress((void**)&qkv,   g_qkv);
    cudaGetSymbolAddress((void**)&counts, g_counts);
    cudaGetSymbolAddress((void**)&toklist, g_toklist);
    cudaGetSymbolAddress((void**)&tokslot, g_tokslot);
    cudaGetSymbolAddress((void**)&tokw2, g_tokw2);

    const int GSMEM_QKV = 2 * (16384 + 2 * 192 * 64);  // NF=6: 81920
    const int GSMEM_OP  = 65536;                        // NF=4
    const int GSMEM1 = 98304;
    cudaFuncSetAttribute((const void*)hmma2<6,1,0>, cudaFuncAttributeMaxDynamicSharedMemorySize, GSMEM_QKV);
    cudaFuncSetAttribute((const void*)hmma2<4,2,1>, cudaFuncAttributeMaxDynamicSharedMemorySize, GSMEM_OP);
    cudaFuncSetAttribute((const void*)hmma1<1,3>, cudaFuncAttributeMaxDynamicSharedMemorySize, GSMEM1);
    cudaFuncSetAttribute((const void*)hmma1<0,0>, cudaFuncAttributeMaxDynamicSharedMemorySize, GSMEM1);
    int attn_smem = (64 * 64 + 64 * 68 + 64 * 64) * 4;
    cudaFuncSetAttribute((const void*)attn_flash, cudaFuncAttributeMaxDynamicSharedMemorySize, attn_smem);

    // Side stream: weight prep (attention splits first, then MoE conversion)
    cudaStream_t s2;
    cudaStreamCreateWithFlags(&s2, cudaStreamNonBlocking);
    cudaEvent_t evFork, evJoinW, evJoin;
    cudaEventCreateWithFlags(&evFork, cudaEventDisableTiming);
    cudaEventCreateWithFlags(&evJoinW, cudaEventDisableTiming);
    cudaEventCreateWithFlags(&evJoin, cudaEventDisableTiming);

    zero_counts<<<1, 32>>>(counts);

    cudaEventRecord(evFork, 0);
    cudaStreamWaitEvent(s2, evFork, 0);
    split_kernel<<<(QKV_O * H_ / 4 + 255) / 256, 256, 0, s2>>>(
        w_qkv, wqh, wql, QKV_O * H_ / 4);
    split_kernel<<<(H_ * H_ / 4 + 255) / 256, 256, 0, s2>>>(
        w_o, woh, wol, H_ * H_ / 4);
    cudaEventRecord(evJoinW, s2);
    cvt_moe_gs<<<112, 256, 0, s2>>>(ws, wsf, w2s, w2f);
    cudaEventRecord(evJoin, s2);

    // main path
    rmsnorm_hl<<<S_, 256>>>(hidden, ln1, xnh, xnl);
    cudaStreamWaitEvent(0, evJoinW, 0);

    // QKV (bf16 3-term, 128x192 tile, single balanced wave: 16x8=128 CTAs)
    hmma2<6,1,0><<<dim3(S_ / 128, QKV_O / 192, 1), 256, GSMEM_QKV>>>(
        xnh, xnl, wqh, wql, qkv, S_, QKV_O, H_, H_, QKV_O, nullptr);

    attn_flash<<<dim3(S_ / 64, NH_), 128, attn_smem>>>(qkv, ath, atl);

    // O proj + residual (bf16 3-term, 128x128 tile)
    hmma2<4,2,1><<<dim3(S_ / 128, H_ / 128, 1), 256, GSMEM_OP>>>(
        ath, atl, woh, wol, resid2, S_, H_, H_, H_, H_, hidden);

    rmsnorm_f16<<<S_, 256>>>(resid2, ln2, tnorm, tnf);
    router_kernel<<<S_ / 8, 256>>>(tnorm, router_w, counts, toklist,
                                   tokslot, tokw2);

    // join: MoE GEMMs need converted weights
    cudaStreamWaitEvent(0, evJoin, 0);

    // MoE up+gate (fp16, gathered A, swiglu fused) -> act fp16
    hmma1<1,3><<<dim3(S_ / 128, 2 * I_ / 128, E_), 256, GSMEM1>>>(
        tnf, wsf, nullptr, S_, 2 * I_, H_, H_, 0,
        counts, toklist, actf,
        0, (size_t)2 * I_ * H_, 0);

    // MoE down (fp16) -> dense per-slot y (fp16)
    hmma1<0,0><<<dim3(S_ / 128, H_ / 128, E_), 256, GSMEM1>>>(
        actf, w2f, yb, S_, H_, I_, I_, H_,
        counts, toklist, nullptr,
        (size_t)S_ * I_, (size_t)H_ * I_, (size_t)S_ * H_);

    // combine: out[tok] = w1*y[slot1] + w2*y[slot2]
    combine_kernel<<<S_, 256>>>(yb, tokslot, tokw2, out);
}

// round 17
// speedup vs baseline: 1.1568x; 1.1568x over previous
#include <cuda_runtime.h>
#include <cuda_bf16.h>
#include <cuda_fp16.h>
#include <math.h>
#include <stdint.h>

#define S_  2048
#define H_  1024
#define NH_ 16
#define NKV_ 4
#define HD_ 64
#define QKV_O 1536
#define I_  2816
#define E_  8
#define WIN_ 512
#define EPS_ 1e-5f

typedef __nv_bfloat16 bf16;
typedef __half f16;
typedef unsigned long long u64;

// ---------------------------------------------------------------------------
// Scratch (static device globals)
// ---------------------------------------------------------------------------
__device__ bf16 g_wqkv_h[QKV_O * H_], g_wqkv_l[QKV_O * H_];
__device__ bf16 g_wo_h[H_ * H_],      g_wo_l[H_ * H_];
__device__ f16  g_ws_f[(size_t)E_ * 2 * I_ * H_];
__device__ f16  g_w2s_f[(size_t)E_ * H_ * I_];
__device__ bf16 g_xn_h[S_ * H_], g_xn_l[S_ * H_];
__device__ bf16 g_at_h[S_ * H_], g_at_l[S_ * H_];
__device__ f16  g_tn_f[S_ * H_];
__device__ float g_tnorm[S_ * H_];
__device__ f16  g_act_f[(size_t)E_ * S_ * I_];
__device__ f16  g_y[(size_t)E_ * S_ * H_];         // per-slot MoE outputs (fp16)
__device__ float g_qkv[S_ * QKV_O];
__device__ int   g_counts[E_];
__device__ int   g_toklist[E_ * S_];
__device__ int   g_tokslot[S_ * 2];
__device__ float g_tokw2[S_ * 2];

// ---------------------------------------------------------------------------
__device__ __forceinline__ uint32_t smem_u32(const void* p) {
    uint32_t a;
    asm("{ .reg .u64 t; cvta.to.shared.u64 t, %1; cvt.u32.u64 %0, t; }"
        : "=r"(a) : "l"(p));
    return a;
}
__device__ __forceinline__ void ldm4(uint32_t& r0, uint32_t& r1,
                                     uint32_t& r2, uint32_t& r3, uint32_t addr) {
    asm volatile("ldmatrix.sync.aligned.m8n8.x4.shared.b16 {%0,%1,%2,%3}, [%4];"
                 : "=r"(r0), "=r"(r1), "=r"(r2), "=r"(r3) : "r"(addr));
}
__device__ __forceinline__ void mma_bf16(float* d, const uint32_t* a,
                                         const uint32_t* b) {
    asm volatile(
        "mma.sync.aligned.m16n8k16.row.col.f32.bf16.bf16.f32 "
        "{%0,%1,%2,%3}, {%4,%5,%6,%7}, {%8,%9}, {%0,%1,%2,%3};"
        : "+f"(d[0]), "+f"(d[1]), "+f"(d[2]), "+f"(d[3])
        : "r"(a[0]), "r"(a[1]), "r"(a[2]), "r"(a[3]), "r"(b[0]), "r"(b[1]));
}
__device__ __forceinline__ void mma_f16(float* d, const uint32_t* a,
                                        const uint32_t* b) {
    asm volatile(
        "mma.sync.aligned.m16n8k16.row.col.f32.f16.f16.f32 "
        "{%0,%1,%2,%3}, {%4,%5,%6,%7}, {%8,%9}, {%0,%1,%2,%3};"
        : "+f"(d[0]), "+f"(d[1]), "+f"(d[2]), "+f"(d[3])
        : "r"(a[0]), "r"(a[1]), "r"(a[2]), "r"(a[3]), "r"(b[0]), "r"(b[1]));
}
__device__ __forceinline__ void cp16(uint32_t dst, const void* src, int sz) {
    asm volatile("cp.async.cg.shared.global [%0], [%1], 16, %2;"
                 :: "r"(dst), "l"(src), "r"(sz));
}
__device__ __forceinline__ void cp_commit() {
    asm volatile("cp.async.commit_group;");
}
__device__ __forceinline__ void cp_wait0() {
    asm volatile("cp.async.wait_group 0;");
}
__device__ __forceinline__ void cp_wait1() {
    asm volatile("cp.async.wait_group 1;");
}

// packed f32x2 helpers
__device__ __forceinline__ u64 pack2(float lo, float hi) {
    u64 r; asm("mov.b64 %0, {%1,%2};" : "=l"(r) : "f"(lo), "f"(hi)); return r;
}
__device__ __forceinline__ void unpack2(u64 v, float& lo, float& hi) {
    asm("mov.b64 {%0,%1}, %2;" : "=f"(lo), "=f"(hi) : "l"(v));
}
__device__ __forceinline__ void ffma2(u64& d, u64 a, u64 b) {
    asm("fma.rn.f32x2 %0, %1, %2, %0;" : "+l"(d) : "l"(a), "l"(b));
}
__device__ __forceinline__ void mulf2(u64& d, u64 a) {
    asm("mul.rn.f32x2 %0, %0, %1;" : "+l"(d) : "l"(a));
}

// split fp32 float4 -> bf16 hi/lo (8B each)
__device__ __forceinline__ void split_store4(float4 v, bf16* hp, bf16* lp) {
    __nv_bfloat162 h01 = __floats2bfloat162_rn(v.x, v.y);
    __nv_bfloat162 h23 = __floats2bfloat162_rn(v.z, v.w);
    float2 f01 = __bfloat1622float2(h01);
    float2 f23 = __bfloat1622float2(h23);
    __nv_bfloat162 l01 = __floats2bfloat162_rn(v.x - f01.x, v.y - f01.y);
    __nv_bfloat162 l23 = __floats2bfloat162_rn(v.z - f23.x, v.w - f23.y);
    *(uint2*)hp = make_uint2(*(uint32_t*)&h01, *(uint32_t*)&h23);
    *(uint2*)lp = make_uint2(*(uint32_t*)&l01, *(uint32_t*)&l23);
}
__device__ __forceinline__ void split1(float v, bf16* hp, bf16* lp) {
    bf16 hb = __float2bfloat16(v);
    *hp = hb;
    *lp = __float2bfloat16(v - __bfloat162float(hb));
}
__device__ __forceinline__ void cvt_store4(float4 v, f16* p) {
    __half2 a = __floats2half2_rn(v.x, v.y);
    __half2 b = __floats2half2_rn(v.z, v.w);
    *(uint2*)p = make_uint2(*(uint32_t*)&a, *(uint32_t*)&b);
}

// ---------------------------------------------------------------------------
// hmma2: bf16 3-term split GEMM (router-critical path).
// CTA tile 128 x (NF*32), BK=32, 8 warps (2m x 4n), warp tile 64 x (NF*8).
// cp.async double-buffered, MAXCTA CTAs/SM.  EPI: 0=store 1=+addsrc
// NF=4: 128-wide tile (O-proj).  NF=6: 192-wide tile (QKV, 1 CTA/SM,
// single balanced wave: grid 16x8=128 CTAs).
// ---------------------------------------------------------------------------
template<int NF, int MAXCTA, int EPI>
__global__ __launch_bounds__(256, MAXCTA)
void hmma2(const bf16* __restrict__ Ah, const bf16* __restrict__ Al,
           const bf16* __restrict__ Bh, const bf16* __restrict__ Bl,
           float* __restrict__ C, int M, int N, int K, int lda, int ldc,
           const float* __restrict__ addsrc)
{
    extern __shared__ char smem[];
    const int TILE_N = NF * 32;
    const int BPS = TILE_N * 64;            // B plane bytes per stage
    const int STAGE = 16384 + 2 * BPS;      // A planes 16KB + 2 B planes

    int m0 = blockIdx.x * 128;
    int n0 = blockIdx.y * TILE_N;

    int tid = threadIdx.x;
    int wid = tid >> 5;
    int lane = tid & 31;
    int warp_m = wid & 1;
    int warp_n = wid >> 1;

    uint32_t sbase = smem_u32(smem);

    auto issue = [&](int c, int buf) {
        int k0 = c * 32;
        #pragma unroll
        for (int l = 0; l < 4 + NF; l++) {
            int seg = tid + l * 256;
            uint32_t dst;
            const bf16* gsrc;
            if (seg < 1024) {               // A planes
                int plane = seg >> 9;
                int rem = seg & 511;
                int row = rem >> 2, ch = rem & 3;
                dst = sbase + buf * STAGE + plane * 8192
                    + row * 64 + ((ch ^ ((row >> 1) & 3)) << 4);
                gsrc = (plane ? Al : Ah) + (size_t)(m0 + row) * lda + k0 + ch * 8;
            } else {                        // B planes
                int s2 = seg - 1024;
                int plane = s2 / (NF * 128);
                int rem = s2 - plane * (NF * 128);
                int row = rem >> 2, ch = rem & 3;
                dst = sbase + buf * STAGE + 16384 + plane * BPS
                    + row * 64 + ((ch ^ ((row >> 1) & 3)) << 4);
                gsrc = (plane ? Bl : Bh) + (size_t)(n0 + row) * K + k0 + ch * 8;
            }
            cp16(dst, gsrc, 16);
        }
        cp_commit();
    };

    float acc[4][NF][4];
    #pragma unroll
    for (int mf = 0; mf < 4; mf++)
        #pragma unroll
        for (int nf = 0; nf < NF; nf++)
            #pragma unroll
            for (int q = 0; q < 4; q++) acc[mf][nf][q] = 0.f;

    const int nc = K / 32;
    issue(0, 0);

    for (int c = 0; c < nc; c++) {
        cp_wait0();
        __syncthreads();
        if (c + 1 < nc) issue(c + 1, (c + 1) & 1);

        uint32_t sb = sbase + (c & 1) * STAGE;
        int mi = lane >> 3, r = lane & 7;

        #pragma unroll
        for (int ks = 0; ks < 2; ks++) {
            uint32_t afh[4][4], bfh[NF][2];
            #pragma unroll
            for (int nfp = 0; nfp < NF / 2; nfp++) {
                int n = warp_n * (NF * 8) + nfp * 16 + ((mi >> 1) << 3) + r;
                int ch = ks * 2 + (mi & 1);
                uint32_t off = (uint32_t)(n * 64 + ((ch ^ ((n >> 1) & 3)) << 4));
                uint32_t r0, r1, r2, r3;
                ldm4(r0, r1, r2, r3, sb + 16384 + off);
                bfh[nfp * 2 + 0][0] = r0; bfh[nfp * 2 + 0][1] = r1;
                bfh[nfp * 2 + 1][0] = r2; bfh[nfp * 2 + 1][1] = r3;
            }
            #pragma unroll
            for (int mf = 0; mf < 4; mf++) {
                int row = warp_m * 64 + mf * 16 + ((mi & 1) << 3) + r;
                int ch = ks * 2 + (mi >> 1);
                uint32_t off = (uint32_t)(row * 64 + ((ch ^ ((row >> 1) & 3)) << 4));
                ldm4(afh[mf][0], afh[mf][1], afh[mf][2], afh[mf][3], sb + off);
            }
            #pragma unroll
            for (int mf = 0; mf < 4; mf++)
                #pragma unroll
                for (int nf = 0; nf < NF; nf++)
                    mma_bf16(acc[mf][nf], afh[mf], bfh[nf]);
            {
                uint32_t bfl[NF][2];
                #pragma unroll
                for (int nfp = 0; nfp < NF / 2; nfp++) {
                    int n = warp_n * (NF * 8) + nfp * 16 + ((mi >> 1) << 3) + r;
                    int ch = ks * 2 + (mi & 1);
                    uint32_t off = (uint32_t)(n * 64 + ((ch ^ ((n >> 1) & 3)) << 4));
                    uint32_t r0, r1, r2, r3;
                    ldm4(r0, r1, r2, r3, sb + 16384 + BPS + off);
                    bfl[nfp * 2 + 0][0] = r0; bfl[nfp * 2 + 0][1] = r1;
                    bfl[nfp * 2 + 1][0] = r2; bfl[nfp * 2 + 1][1] = r3;
                }
                #pragma unroll
                for (int mf = 0; mf < 4; mf++)
                    #pragma unroll
                    for (int nf = 0; nf < NF; nf++)
                        mma_bf16(acc[mf][nf], afh[mf], bfl[nf]);
            }
            {
                uint32_t afl[4][4];
                #pragma unroll
                for (int mf = 0; mf < 4; mf++) {
                    int row = warp_m * 64 + mf * 16 + ((mi & 1) << 3) + r;
                    int ch = ks * 2 + (mi >> 1);
                    uint32_t off = (uint32_t)(row * 64 + ((ch ^ ((row >> 1) & 3)) << 4));
                    ldm4(afl[mf][0], afl[mf][1], afl[mf][2], afl[mf][3], sb + 8192 + off);
                }
                #pragma unroll
                for (int mf = 0; mf < 4; mf++)
                    #pragma unroll
                    for (int nf = 0; nf < NF; nf++)
                        mma_bf16(acc[mf][nf], afl[mf], bfh[nf]);
            }
        }
    }

    int lr = lane >> 2;
    int lc = (lane & 3) * 2;
    #pragma unroll
    for (int mf = 0; mf < 4; mf++) {
        int r0g = m0 + warp_m * 64 + mf * 16 + lr;
        int r1g = r0g + 8;
        #pragma unroll
        for (int nf = 0; nf < NF; nf++) {
            int col = n0 + warp_n * (NF * 8) + nf * 8 + lc;
            float2 v = make_float2(acc[mf][nf][0], acc[mf][nf][1]);
            float2 w = make_float2(acc[mf][nf][2], acc[mf][nf][3]);
            if (EPI == 1) {
                const float* a2 = addsrc + (size_t)r0g * ldc + col;
                const float* b2 = addsrc + (size_t)r1g * ldc + col;
                v.x += a2[0]; v.y += a2[1];
                w.x += b2[0]; w.y += b2[1];
            }
            *(float2*)(C + (size_t)r0g * ldc + col) = v;
            *(float2*)(C + (size_t)r1g * ldc + col) = w;
        }
    }
}

// ---------------------------------------------------------------------------
// hmma1: plain fp16 GEMM (MoE path). 128x128 tile, BK=64, 8 warps,
// 3-stage cp.async pipeline, 2 CTAs/SM.
// GATHER: A rows via toklist.
// EPI: 0=dense per-slot fp16 store to C (ldc)  3=swiglu->act fp16
// ---------------------------------------------------------------------------
template<int GATHER, int EPI>
__global__ __launch_bounds__(256, 2)
void hmma1(const f16* __restrict__ A, const f16* __restrict__ B,
           f16* __restrict__ C, int M, int N, int K, int lda, int ldc,
           const int* __restrict__ counts,
           const int* __restrict__ toklist,
           f16* __restrict__ actF,
           size_t sA, size_t sB, size_t sC)
{
    extern __shared__ char smem[];
    __shared__ int rowsS[128];

    int e = blockIdx.z;
    int Mlim = counts[e];
    int m0 = blockIdx.x * 128;
    if (m0 >= Mlim) return;
    int n0 = blockIdx.y * 128;
    const f16* Ae = A + sA * e;
    const f16* Be = B + sB * e;
    f16*       Ce = C ? C + sC * e : nullptr;

    int tid = threadIdx.x;
    int wid = tid >> 5;
    int lane = tid & 31;
    int warp_m = wid & 1;
    int warp_n = wid >> 1;

    if (GATHER) {
        if (tid < 128)
            rowsS[tid] = (m0 + tid < Mlim) ? toklist[e * S_ + m0 + tid] : -1;
        __syncthreads();
    }

    uint32_t sbase = smem_u32(smem);

    auto issue = [&](int c, int buf) {
        int k0 = c * 64;
        #pragma unroll
        for (int l = 0; l < 8; l++) {
            int seg = tid + l * 256;
            int plane = seg >> 10;
            int row = (seg >> 3) & 127;
            int ch = seg & 7;
            uint32_t dst = sbase + buf * 32768 + plane * 16384
                         + row * 128 + ((ch ^ (row & 7)) << 4);
            const f16* gsrc;
            int sz = 16;
            if (plane == 0) {
                int gr;
                if (GATHER) {
                    gr = rowsS[row];
                    if (gr < 0) { gr = 0; sz = 0; }
                } else {
                    gr = m0 + row;
                    if (gr >= Mlim) { gr = 0; sz = 0; }
                }
                gsrc = Ae + (size_t)gr * lda + k0 + ch * 8;
            } else {
                gsrc = Be + (size_t)(n0 + row) * K + k0 + ch * 8;
            }
            cp16(dst, gsrc, sz);
        }
        cp_commit();
    };

    float acc[4][4][4] = {};
    const int nc = K / 64;
    issue(0, 0);
    if (nc > 1) issue(1, 1);

    for (int c = 0; c < nc; c++) {
        if (c + 1 < nc) cp_wait1(); else cp_wait0();
        __syncthreads();
        if (c + 2 < nc) issue(c + 2, (c + 2) % 3);

        uint32_t sb = sbase + (c % 3) * 32768;
        int mi = lane >> 3, r = lane & 7;

        #pragma unroll
        for (int ks = 0; ks < 4; ks++) {
            uint32_t af[4][4], bf[4][2];
            #pragma unroll
            for (int nfp = 0; nfp < 2; nfp++) {
                int n = warp_n * 32 + nfp * 16 + ((mi >> 1) << 3) + r;
                int ch = ks * 2 + (mi & 1);
                uint32_t off = (uint32_t)(n * 128 + ((ch ^ (n & 7)) << 4));
                uint32_t r0, r1, r2, r3;
                ldm4(r0, r1, r2, r3, sb + 16384 + off);
                bf[nfp * 2 + 0][0] = r0; bf[nfp * 2 + 0][1] = r1;
                bf[nfp * 2 + 1][0] = r2; bf[nfp * 2 + 1][1] = r3;
            }
            #pragma unroll
            for (int mf = 0; mf < 4; mf++) {
                int row = warp_m * 64 + mf * 16 + ((mi & 1) << 3) + r;
                int ch = ks * 2 + (mi >> 1);
                uint32_t off = (uint32_t)(row * 128 + ((ch ^ (row & 7)) << 4));
                ldm4(af[mf][0], af[mf][1], af[mf][2], af[mf][3], sb + off);
            }
            #pragma unroll
            for (int mf = 0; mf < 4; mf++)
                #pragma unroll
                for (int nf = 0; nf < 4; nf++)
                    mma_f16(acc[mf][nf], af[mf], bf[nf]);
        }
    }

    int lr = lane >> 2;
    int lc = (lane & 3) * 2;

    if (EPI == 3) {
        __syncthreads();
        float (*Us)[65] = (float (*)[65])smem;
        if (warp_n >= 2) {
            #pragma unroll
            for (int mf = 0; mf < 4; mf++) {
                int rl0 = warp_m * 64 + mf * 16 + lr;
                #pragma unroll
                for (int nf = 0; nf < 4; nf++) {
                    int j = (warp_n - 2) * 32 + nf * 8 + lc;
                    Us[rl0][j]         = acc[mf][nf][0];
                    Us[rl0][j + 1]     = acc[mf][nf][1];
                    Us[rl0 + 8][j]     = acc[mf][nf][2];
                    Us[rl0 + 8][j + 1] = acc[mf][nf][3];
                }
            }
        }
        __syncthreads();
        if (warp_n < 2) {
            int colbase = n0 >> 1;
            #pragma unroll
            for (int mf = 0; mf < 4; mf++) {
                int rl0 = warp_m * 64 + mf * 16 + lr;
                #pragma unroll
                for (int half = 0; half < 2; half++) {
                    int rl = rl0 + half * 8;
                    int m = m0 + rl;
                    if (m >= Mlim) continue;
                    size_t rowoff = ((size_t)e * S_ + m) * I_ + colbase;
                    #pragma unroll
                    for (int nf = 0; nf < 4; nf++) {
                        int j = warp_n * 32 + nf * 8 + lc;
                        #pragma unroll
                        for (int q = 0; q < 2; q++) {
                            float g = acc[mf][nf][half * 2 + q];
                            float u = Us[rl][j + q];
                            float a = g / (1.f + __expf(-g)) * u;
                            actF[rowoff + j + q] = __float2half_rn(a);
                        }
                    }
                }
            }
        }
        return;
    }

    // EPI == 0: dense per-slot fp16 store
    #pragma unroll
    for (int mf = 0; mf < 4; mf++) {
        int r0g = m0 + warp_m * 64 + mf * 16 + lr;
        int r1g = r0g + 8;
        #pragma unroll
        for (int nf = 0; nf < 4; nf++) {
            int col = n0 + warp_n * 32 + nf * 8 + lc;
            if (r0g < Mlim) {
                __half2 h = __floats2half2_rn(acc[mf][nf][0], acc[mf][nf][1]);
                *(uint32_t*)(Ce + (size_t)r0g * ldc + col) = *(uint32_t*)&h;
            }
            if (r1g < Mlim) {
                __half2 h = __floats2half2_rn(acc[mf][nf][2], acc[mf][nf][3]);
                *(uint32_t*)(Ce + (size_t)r1g * ldc + col) = *(uint32_t*)&h;
            }
        }
    }
}

// ---------------------------------------------------------------------------
__global__ void split_kernel(const float* __restrict__ src,
                             bf16* __restrict__ h, bf16* __restrict__ l,
                             size_t n4) {
    size_t i = (size_t)blockIdx.x * blockDim.x + threadIdx.x;
    if (i >= n4) return;
    float4 v = ((const float4*)src)[i];
    split_store4(v, h + i * 4, l + i * 4);
}

__global__ void cvt_kernel(const float* __restrict__ src,
                           f16* __restrict__ d, size_t n4) {
    size_t i = (size_t)blockIdx.x * blockDim.x + threadIdx.x;
    if (i >= n4) return;
    float4 v = ((const float4*)src)[i];
    cvt_store4(v, d + i * 4);
}

// ws -> fp16 with gate/up interleave permutation (full-grid, DRAM-saturating)
__global__ void cvt_ws_perm(const float* __restrict__ ws,
                            f16* __restrict__ d) {
    int e = blockIdx.z, p = blockIdx.y;
    int t = p >> 7, r = p & 127;
    int src = (r < 64) ? (t * 64 + r) : (I_ + t * 64 + (r - 64));
    const float* srow = ws + ((size_t)e * 2 * I_ + src) * H_;
    f16* dr = d + ((size_t)e * 2 * I_ + p) * H_;
    int i = threadIdx.x * 4;
    float4 v = *(const float4*)(srow + i);
    cvt_store4(v, dr + i);
}

// ---------------------------------------------------------------------------
__global__ void zero_counts(int* counts) {
    if (threadIdx.x < E_) counts[threadIdx.x] = 0;
}

// RMSNorm -> bf16 hi/lo planes (ln1 path)
__global__ void rmsnorm_hl(const float* __restrict__ x,
                           const float* __restrict__ w,
                           bf16* __restrict__ yh, bf16* __restrict__ yl) {
    int row = blockIdx.x;
    int tid = threadIdx.x;
    __shared__ float red[256];
    const float* xr = x + (size_t)row * H_;
    float s = 0.0f;
    for (int c = tid; c < H_; c += 256) { float v = xr[c]; s += v * v; }
    red[tid] = s; __syncthreads();
    for (int o = 128; o > 0; o >>= 1) {
        if (tid < o) red[tid] += red[tid + o];
        __syncthreads();
    }
    float inv = rsqrtf(red[0] / (float)H_ + EPS_);
    for (int c = tid * 4; c < H_; c += 1024) {
        float4 v = *(const float4*)(xr + c);
        float4 wv = *(const float4*)(w + c);
        v.x *= inv * wv.x; v.y *= inv * wv.y;
        v.z *= inv * wv.z; v.w *= inv * wv.w;
        split_store4(v, yh + (size_t)row * H_ + c, yl + (size_t)row * H_ + c);
    }
}

// RMSNorm -> fp32 (router input — MUST stay fp32) + fp16 plane (MoE A)
__global__ void rmsnorm_f16(const float* __restrict__ x,
                            const float* __restrict__ w,
                            float* __restrict__ y,
                            f16* __restrict__ yf) {
    int row = blockIdx.x;
    int tid = threadIdx.x;
    __shared__ float red[256];
    const float* xr = x + (size_t)row * H_;
    float s = 0.0f;
    for (int c = tid; c < H_; c += 256) { float v = xr[c]; s += v * v; }
    red[tid] = s; __syncthreads();
    for (int o = 128; o > 0; o >>= 1) {
        if (tid < o) red[tid] += red[tid + o];
        __syncthreads();
    }
    float inv = rsqrtf(red[0] / (float)H_ + EPS_);
    for (int c = tid * 4; c < H_; c += 1024) {
        float4 v = *(const float4*)(xr + c);
        float4 wv = *(const float4*)(w + c);
        v.x *= inv * wv.x; v.y *= inv * wv.y;
        v.z *= inv * wv.z; v.w *= inv * wv.w;
        *(float4*)(y + (size_t)row * H_ + c) = v;
        cvt_store4(v, yf + (size_t)row * H_ + c);
    }
}

// ---------------------------------------------------------------------------
// Flash attention (fp32, f32x2-packed math): 128 threads, 8x4 register tile
// ---------------------------------------------------------------------------
__global__ __launch_bounds__(128)
void attn_flash(const float* __restrict__ qkv,
                bf16* __restrict__ oh, bf16* __restrict__ ol) {
    extern __shared__ float smf[];
    float* Qs  = smf;
    float* KPs = smf + 4096;
    float* Vs  = smf + 4096 + 64 * 68;

    int qt = blockIdx.x, h = blockIdx.y;
    int q0 = qt * 64;
    int kvh = h >> 2;
    int tid = threadIdx.x;
    int tx = tid & 15, ty = tid >> 4;

    #pragma unroll
    for (int l = 0; l < 8; l++) {
        int idx = tid + l * 128;
        int r = idx >> 4, dq = (idx & 15) * 4;
        *(float4*)&Qs[r * 64 + dq] =
            *(const float4*)&qkv[(size_t)(q0 + r) * QKV_O + h * 64 + dq];
    }

    u64 acc2[8][4];
    #pragma unroll
    for (int i = 0; i < 8; i++)
        #pragma unroll
        for (int j = 0; j < 4; j++) acc2[i][j] = 0ull;
    float rm[8], rl[8];
    #pragma unroll
    for (int i = 0; i < 8; i++) { rm[i] = -1e30f; rl[i] = 0.f; }

    int t0 = (q0 > 511) ? ((q0 - 511) >> 6) : 0;
    for (int kt = t0; kt <= qt; kt++) {
        int j0 = kt * 64;
        __syncthreads();
        #pragma unroll
        for (int l = 0; l < 8; l++) {
            int idx = tid + l * 128;
            int r = idx >> 4, dq = (idx & 15) * 4;
            *(float4*)&KPs[r * 68 + dq] =
                *(const float4*)&qkv[(size_t)(j0 + r) * QKV_O + H_ + kvh * 64 + dq];
            *(float4*)&Vs[r * 64 + dq] =
                *(const float4*)&qkv[(size_t)(j0 + r) * QKV_O + H_ + NKV_ * HD_ + kvh * 64 + dq];
        }
        __syncthreads();

        u64 s2[8][4];
        #pragma unroll
        for (int i = 0; i < 8; i++)
            #pragma unroll
            for (int j = 0; j < 4; j++) s2[i][j] = 0ull;
        #pragma unroll
        for (int d0 = 0; d0 < 64; d0 += 4) {
            u64 ka[4], kb[4];
            #pragma unroll
            for (int j = 0; j < 4; j++) {
                const u64* kp = (const u64*)&KPs[(tx + 16 * j) * 68 + d0];
                ka[j] = kp[0]; kb[j] = kp[1];
            }
            #pragma unroll
            for (int i = 0; i < 8; i++) {
                const u64* qp = (const u64*)&Qs[(ty * 8 + i) * 64 + d0];
                u64 qa = qp[0], qb = qp[1];
                #pragma unroll
                for (int j = 0; j < 4; j++) {
                    ffma2(s2[i][j], qa, ka[j]);
                    ffma2(s2[i][j], qb, kb[j]);
                }
            }
        }
        __syncthreads();

        #pragma unroll
        for (int i = 0; i < 8; i++) {
            int iq = q0 + ty * 8 + i;
            float p[4], s[4];
            float tm = -1e30f;
            #pragma unroll
            for (int j = 0; j < 4; j++) {
                float lo, hi;
                unpack2(s2[i][j], lo, hi);
                int jk = j0 + tx + 16 * j;
                bool ok = (jk <= iq) && (iq - jk < WIN_);
                s[j] = ok ? (lo + hi) * 0.125f : -1e30f;
                tm = fmaxf(tm, s[j]);
            }
            #pragma unroll
            for (int o = 1; o < 16; o <<= 1)
                tm = fmaxf(tm, __shfl_xor_sync(0xffffffffu, tm, o));
            float mn = fmaxf(rm[i], tm);
            float alpha = __expf(rm[i] - mn);
            rm[i] = mn;
            float ps = 0.f;
            #pragma unroll
            for (int j = 0; j < 4; j++) { p[j] = __expf(s[j] - mn); ps += p[j]; }
            #pragma unroll
            for (int o = 1; o < 16; o <<= 1)
                ps += __shfl_xor_sync(0xffffffffu, ps, o);
            rl[i] = rl[i] * alpha + ps;
            u64 alpha2 = pack2(alpha, alpha);
            #pragma unroll
            for (int j = 0; j < 4; j++) {
                mulf2(acc2[i][j], alpha2);
                KPs[(ty * 8 + i) * 68 + tx + 16 * j] = p[j];
            }
        }
        __syncthreads();

        #pragma unroll 2
        for (int n = 0; n < 64; n += 2) {
            u64 pv2[8];
            #pragma unroll
            for (int i = 0; i < 8; i++)
                pv2[i] = *(const u64*)&KPs[(ty * 8 + i) * 68 + n];
            u64 v2[4];
            #pragma unroll
            for (int j = 0; j < 4; j++)
                v2[j] = pack2(Vs[n * 64 + tx + 16 * j],
                              Vs[(n + 1) * 64 + tx + 16 * j]);
            #pragma unroll
            for (int i = 0; i < 8; i++)
                #pragma unroll
                for (int j = 0; j < 4; j++)
                    ffma2(acc2[i][j], pv2[i], v2[j]);
        }
    }

    #pragma unroll
    for (int i = 0; i < 8; i++) {
        float inv = 1.0f / rl[i];
        size_t base = (size_t)(q0 + ty * 8 + i) * H_ + h * 64;
        #pragma unroll
        for (int j = 0; j < 4; j++) {
            float lo, hi;
            unpack2(acc2[i][j], lo, hi);
            split1((lo + hi) * inv, &oh[base + tx + 16 * j], &ol[base + tx + 16 * j]);
        }
    }
}

// ---------------------------------------------------------------------------
// Router reads fp32 tnorm (router-critical precision)
__global__ void router_kernel(const float* __restrict__ t,
                              const float* __restrict__ rw,
                              int* counts, int* toklist,
                              int* tokslot, float* tokw2) {
    int warp = threadIdx.x >> 5;
    int lane = threadIdx.x & 31;
    int tok = blockIdx.x * 8 + warp;
    if (tok >= S_) return;
    const float* tr = t + (size_t)tok * H_;
    float logits[E_];
    for (int e = 0; e < E_; e++) {
        float s = 0.0f;
        for (int k = lane; k < H_; k += 32) s += tr[k] * rw[e * H_ + k];
        for (int o = 16; o > 0; o >>= 1) s += __shfl_xor_sync(0xffffffff, s, o);
        logits[e] = s;
    }
    if (lane == 0) {
        float mx = logits[0];
        for (int e = 1; e < E_; e++) mx = fmaxf(mx, logits[e]);
        float p[E_], sum = 0.0f;
        for (int e = 0; e < E_; e++) { p[e] = __expf(logits[e] - mx); sum += p[e]; }
        float invs = 1.0f / sum;
        for (int e = 0; e < E_; e++) p[e] *= invs;
        int b1 = 0;
        for (int e = 1; e < E_; e++) if (p[e] > p[b1]) b1 = e;
        int b2 = -1;
        for (int e = 0; e < E_; e++) {
            if (e == b1) continue;
            if (b2 < 0 || p[e] > p[b2]) b2 = e;
        }
        int pos1 = atomicAdd(&counts[b1], 1);
        toklist[b1 * S_ + pos1] = tok;
        tokslot[tok * 2] = b1 * S_ + pos1; tokw2[tok * 2] = p[b1];
        int pos2 = atomicAdd(&counts[b2], 1);
        toklist[b2 * S_ + pos2] = tok;
        tokslot[tok * 2 + 1] = b2 * S_ + pos2; tokw2[tok * 2 + 1] = p[b2];
    }
}

// out[tok] = w1 * y[slot1] + w2 * y[slot2]   (y is fp16)
__global__ void combine_kernel(const f16* __restrict__ y,
                               const int* __restrict__ tokslot,
                               const float* __restrict__ tokw2,
                               float* __restrict__ out) {
    int tok = blockIdx.x;
    int c = threadIdx.x * 4;
    int s1 = tokslot[tok * 2], s2 = tokslot[tok * 2 + 1];
    float w1 = tokw2[tok * 2], w2 = tokw2[tok * 2 + 1];
    uint2 ar = *(const uint2*)&y[(size_t)s1 * H_ + c];
    uint2 br = *(const uint2*)&y[(size_t)s2 * H_ + c];
    float2 a0 = __half22float2(*(__half2*)&ar.x);
    float2 a1 = __half22float2(*(__half2*)&ar.y);
    float2 b0 = __half22float2(*(__half2*)&br.x);
    float2 b1 = __half22float2(*(__half2*)&br.y);
    float4 o;
    o.x = w1 * a0.x + w2 * b0.x;
    o.y = w1 * a0.y + w2 * b0.y;
    o.z = w1 * a1.x + w2 * b1.x;
    o.w = w1 * a1.y + w2 * b1.y;
    *(float4*)&out[(size_t)tok * H_ + c] = o;
}

// ---------------------------------------------------------------------------
extern "C" void kernel_launch(void* const* d_in, const int* in_sizes, int n_in,
                              void* d_out, int out_size) {
    const float* hidden   = (const float*)d_in[0];
    const float* w_qkv    = (const float*)d_in[2];
    const float* w_o      = (const float*)d_in[3];
    const float* router_w = (const float*)d_in[4];
    const float* ws       = (const float*)d_in[5];
    const float* w2s      = (const float*)d_in[6];
    const float* ln1      = (const float*)d_in[7];
    const float* ln2      = (const float*)d_in[8];

    float* out    = (float*)d_out;
    float* resid2 = out + (size_t)S_ * H_;

    bf16 *wqh, *wql, *woh, *wol, *xnh, *xnl, *ath, *atl;
    f16 *wsf, *w2f, *tnf, *actf, *yb;
    float *qkv, *tnorm, *tokw2;
    int *counts, *toklist, *tokslot;
    cudaGetSymbolAddress((void**)&wqh, g_wqkv_h); cudaGetSymbolAddress((void**)&wql, g_wqkv_l);
    cudaGetSymbolAddress((void**)&woh, g_wo_h);   cudaGetSymbolAddress((void**)&wol, g_wo_l);
    cudaGetSymbolAddress((void**)&wsf, g_ws_f);
    cudaGetSymbolAddress((void**)&w2f, g_w2s_f);
    cudaGetSymbolAddress((void**)&xnh, g_xn_h);   cudaGetSymbolAddress((void**)&xnl, g_xn_l);
    cudaGetSymbolAddress((void**)&ath, g_at_h);   cudaGetSymbolAddress((void**)&atl, g_at_l);
    cudaGetSymbolAddress((void**)&tnf, g_tn_f);
    cudaGetSymbolAddress((void**)&tnorm, g_tnorm);
    cudaGetSymbolAddress((void**)&actf, g_act_f);
    cudaGetSymbolAddress((void**)&yb, g_y);
    cudaGetSymbolAddress((void**)&qkv,   g_qkv);
    cudaGetSymbolAddress((void**)&counts, g_counts);
    cudaGetSymbolAddress((void**)&toklist, g_toklist);
    cudaGetSymbolAddress((void**)&tokslot, g_tokslot);
    cudaGetSymbolAddress((void**)&tokw2, g_tokw2);

    const int GSMEM_QKV = 2 * (16384 + 2 * 192 * 64);  // NF=6: 81920
    const int GSMEM_OP  = 65536;                        // NF=4
    const int GSMEM1 = 98304;
    cudaFuncSetAttribute((const void*)hmma2<6,1,0>, cudaFuncAttributeMaxDynamicSharedMemorySize, GSMEM_QKV);
    cudaFuncSetAttribute((const void*)hmma2<4,2,1>, cudaFuncAttributeMaxDynamicSharedMemorySize, GSMEM_OP);
    cudaFuncSetAttribute((const void*)hmma1<1,3>, cudaFuncAttributeMaxDynamicSharedMemorySize, GSMEM1);
    cudaFuncSetAttribute((const void*)hmma1<0,0>, cudaFuncAttributeMaxDynamicSharedMemorySize, GSMEM1);
    int attn_smem = (64 * 64 + 64 * 68 + 64 * 64) * 4;
    cudaFuncSetAttribute((const void*)attn_flash, cudaFuncAttributeMaxDynamicSharedMemorySize, attn_smem);

    zero_counts<<<1, 32>>>(counts);

    // Serial full-width prepasses (measured DRAM-saturating; no stream fork —
    // overlap experiments showed contention costs exceed the hidden time).
    split_kernel<<<(QKV_O * H_ / 4 + 255) / 256, 256>>>(
        w_qkv, wqh, wql, QKV_O * H_ / 4);
    split_kernel<<<(H_ * H_ / 4 + 255) / 256, 256>>>(
        w_o, woh, wol, H_ * H_ / 4);
    cvt_ws_perm<<<dim3(1, 2 * I_, E_), 256>>>(ws, wsf);
    cvt_kernel<<<(int)(((size_t)E_ * H_ * I_ / 4 + 255) / 256), 256>>>(
        w2s, w2f, (size_t)E_ * H_ * I_ / 4);

    rmsnorm_hl<<<S_, 256>>>(hidden, ln1, xnh, xnl);

    // QKV (bf16 3-term, 128x192 tile, single balanced wave: 16x8=128 CTAs)
    hmma2<6,1,0><<<dim3(S_ / 128, QKV_O / 192, 1), 256, GSMEM_QKV>>>(
        xnh, xnl, wqh, wql, qkv, S_, QKV_O, H_, H_, QKV_O, nullptr);

    attn_flash<<<dim3(S_ / 64, NH_), 128, attn_smem>>>(qkv, ath, atl);

    // O proj + residual (bf16 3-term, 128x128 tile)
    hmma2<4,2,1><<<dim3(S_ / 128, H_ / 128, 1), 256, GSMEM_OP>>>(
        ath, atl, woh, wol, resid2, S_, H_, H_, H_, H_, hidden);

    rmsnorm_f16<<<S_, 256>>>(resid2, ln2, tnorm, tnf);
    router_kernel<<<S_ / 8, 256>>>(tnorm, router_w, counts, toklist,
                                   tokslot, tokw2);

    // MoE up+gate (fp16, gathered A, swiglu fused) -> act fp16
    hmma1<1,3><<<dim3(S_ / 128, 2 * I_ / 128, E_), 256, GSMEM1>>>(
        tnf, wsf, nullptr, S_, 2 * I_, H_, H_, 0,
        counts, toklist, actf,
        0, (size_t)2 * I_ * H_, 0);

    // MoE down (fp16) -> dense per-slot y (fp16)
    hmma1<0,0><<<dim3(S_ / 128, H_ / 128, E_), 256, GSMEM1>>>(
        actf, w2f, yb, S_, H_, I_, I_, H_,
        counts, toklist, nullptr,
        (size_t)S_ * I_, (size_t)H_ * I_, (size_t)S_ * H_);

    // combine: out[tok] = w1*y[slot1] + w2*y[slot2]
    combine_kernel<<<S_, 256>>>(yb, tokslot, tokw2, out);
}